// round 4
// baseline (speedup 1.0000x reference)
#include <cuda_runtime.h>
#include <cstdint>

#define N_NODES 50000
#define MAX_E   400000
#define D_IN   600
#define D_H    628     // hidden width (layer1 out)
#define D_HP   640     // padded hidden width (128B-aligned rows)
#define D_OUT  64      // layer2 out

// ---------------- scratch (alloc-free: __device__ globals) ----------------
__device__ float g_buf1[(size_t)N_NODES * D_HP];  // Hs1
__device__ float g_buf2[(size_t)N_NODES * D_HP];  // Z1
__device__ float g_buf3[(size_t)N_NODES * D_OUT]; // Hs2
__device__ float g_buf4[(size_t)N_NODES * D_OUT]; // Z2
__device__ float g_dinv[N_NODES];
__device__ int   g_deg[N_NODES];
__device__ int   g_rowstart[N_NODES + 1];
__device__ int   g_cur[N_NODES];
__device__ int   g_adj[MAX_E];

// ---------------- packed f32x2 helpers (sm_100: 2x FP32 rate, PTX-only) ----------------
__device__ __forceinline__ unsigned long long fma_f32x2(unsigned long long a,
                                                        unsigned long long b,
                                                        unsigned long long c) {
    unsigned long long d;
    asm("fma.rn.f32x2 %0, %1, %2, %3;" : "=l"(d) : "l"(a), "l"(b), "l"(c));
    return d;
}
__device__ __forceinline__ unsigned long long dup_f32(float x) {
    unsigned long long d;
    asm("mov.b64 %0, {%1, %1};" : "=l"(d) : "r"(__float_as_uint(x)));
    return d;
}
__device__ __forceinline__ float2 unpk_f32x2(unsigned long long v) {
    float2 r;
    asm("mov.b64 {%0, %1}, %2;" : "=f"(r.x), "=f"(r.y) : "l"(v));
    return r;
}

// ---------------- degree / dinv ----------------
__global__ void k_count(const int* __restrict__ dst, int E, int* __restrict__ deg) {
    int e = blockIdx.x * blockDim.x + threadIdx.x;
    if (e < E) atomicAdd(&deg[dst[e]], 1);
}

__global__ void k_dinv(const int* __restrict__ deg, float* __restrict__ dinv, int n) {
    int i = blockIdx.x * blockDim.x + threadIdx.x;
    if (i < n) dinv[i] = rsqrtf((float)(deg[i] + 1)); // +1 self loop
}

// ---------------- exclusive prefix sum of degrees (single block) ----------------
__global__ __launch_bounds__(1024)
void k_scan(const int* __restrict__ deg, int* __restrict__ rowstart, int n) {
    __shared__ int partial[1024];
    const int CH = (n + 1023) / 1024;
    int t = threadIdx.x;
    int t0 = t * CH;
    int s = 0;
    for (int i = 0; i < CH; i++) {
        int idx = t0 + i;
        if (idx < n) s += deg[idx];
    }
    partial[t] = s;
    __syncthreads();
    for (int off = 1; off < 1024; off <<= 1) {
        int v = partial[t];
        int u = (t >= off) ? partial[t - off] : 0;
        __syncthreads();
        partial[t] = v + u;
        __syncthreads();
    }
    int base = (t == 0) ? 0 : partial[t - 1];
    for (int i = 0; i < CH; i++) {
        int idx = t0 + i;
        if (idx < n) { rowstart[idx] = base; base += deg[idx]; }
    }
    if (t == 0) rowstart[n] = partial[1023];
}

// ---------------- CSR fill: adj grouped by dst ----------------
__global__ void k_fill(const int* __restrict__ src, const int* __restrict__ dst, int E,
                       const int* __restrict__ rowstart, int* __restrict__ cur,
                       int* __restrict__ adj) {
    int e = blockIdx.x * blockDim.x + threadIdx.x;
    if (e >= E) return;
    int d = dst[e];
    int p = atomicAdd(&cur[d], 1);
    adj[rowstart[d] + p] = src[e];
}

// ---------------- fused GEMM1: Hs = dinv[row] * (A @ B) ----------------
// 128x128 tile, 256 threads, 8x8 micro-tile via packed f32x2 (8x4 packed FMAs).
__global__ __launch_bounds__(256)
void k_gemm1(const float* __restrict__ A, int lda,
             const float* __restrict__ B, int ldb,
             int M, int Kloop, int Kvalid, int Nvalid,
             const float* __restrict__ dinv,
             float* __restrict__ Hs, int ldo)
{
    __shared__ float As[8][128];
    __shared__ float Bs[8][128];
    const int tid = threadIdx.x;
    const int m0 = blockIdx.x * 128;
    const int n0 = blockIdx.y * 128;
    const int tx = tid & 15;
    const int ty = tid >> 4;
    const int a_mm = tid >> 1;
    const int a_kq = (tid & 1) << 2;
    const int b_kk = tid >> 5;
    const int b_nn = (tid & 31) << 2;

    unsigned long long acc2[8][4];   // each holds 2 adjacent N columns
#pragma unroll
    for (int i = 0; i < 8; i++)
#pragma unroll
        for (int j = 0; j < 4; j++) acc2[i][j] = 0ull;

    const int a_row = m0 + a_mm;
    const bool a_ok = a_row < M;
    const float* Aptr = A + (size_t)a_row * lda + a_kq;

    float4 av = make_float4(0.f, 0.f, 0.f, 0.f);
    float bv[4] = {0.f, 0.f, 0.f, 0.f};
    {
        if (a_ok) av = *(const float4*)(Aptr);
        if (b_kk < Kvalid) {
#pragma unroll
            for (int q = 0; q < 4; q++) {
                int n = n0 + b_nn + q;
                bv[q] = (n < Nvalid) ? B[(size_t)b_kk * ldb + n] : 0.f;
            }
        }
    }

    for (int k0 = 0; k0 < Kloop; k0 += 8) {
        As[a_kq + 0][a_mm] = av.x;
        As[a_kq + 1][a_mm] = av.y;
        As[a_kq + 2][a_mm] = av.z;
        As[a_kq + 3][a_mm] = av.w;
        *(float4*)(&Bs[b_kk][b_nn]) = make_float4(bv[0], bv[1], bv[2], bv[3]);
        __syncthreads();

        const int kn = k0 + 8;
        float4 av_n = make_float4(0.f, 0.f, 0.f, 0.f);
        float bv_n[4] = {0.f, 0.f, 0.f, 0.f};
        if (kn < Kloop) {
            if (a_ok) av_n = *(const float4*)(Aptr + kn);
            int bk = kn + b_kk;
            if (bk < Kvalid) {
#pragma unroll
                for (int q = 0; q < 4; q++) {
                    int n = n0 + b_nn + q;
                    bv_n[q] = (n < Nvalid) ? B[(size_t)bk * ldb + n] : 0.f;
                }
            }
        }

#pragma unroll
        for (int kk = 0; kk < 8; ++kk) {
            float4 a0 = *(const float4*)(&As[kk][ty * 8]);
            float4 a1 = *(const float4*)(&As[kk][ty * 8 + 4]);
            const unsigned long long* Bp =
                (const unsigned long long*)(&Bs[kk][tx * 8]); // 32B-aligned
            unsigned long long bp[4] = {Bp[0], Bp[1], Bp[2], Bp[3]};
            float am[8] = {a0.x, a0.y, a0.z, a0.w, a1.x, a1.y, a1.z, a1.w};
#pragma unroll
            for (int i = 0; i < 8; i++) {
                unsigned long long ad = dup_f32(am[i]);
#pragma unroll
                for (int j = 0; j < 4; j++)
                    acc2[i][j] = fma_f32x2(ad, bp[j], acc2[i][j]);
            }
        }
        __syncthreads();
        av = av_n;
#pragma unroll
        for (int q = 0; q < 4; q++) bv[q] = bv_n[q];
    }

    const int ldo4 = ldo >> 2;
#pragma unroll
    for (int i = 0; i < 8; i++) {
        int row = m0 + ty * 8 + i;
        if (row < M) {
            float di = dinv[row];
            float2 c0 = unpk_f32x2(acc2[i][0]);
            float2 c1 = unpk_f32x2(acc2[i][1]);
            float2 c2 = unpk_f32x2(acc2[i][2]);
            float2 c3 = unpk_f32x2(acc2[i][3]);
            size_t off = (size_t)row * ldo4 + (n0 >> 2) + tx * 2;
            ((float4*)Hs)[off]     = make_float4(c0.x * di, c0.y * di,
                                                 c1.x * di, c1.y * di);
            ((float4*)Hs)[off + 1] = make_float4(c2.x * di, c2.y * di,
                                                 c3.x * di, c3.y * di);
        }
    }
}

// ---------------- GEMM2 (N=64): 128x64 tile, 8x4 micro-tile via f32x2 ----------------
__global__ __launch_bounds__(256)
void k_gemm2(const float* __restrict__ A, int lda,
             const float* __restrict__ B, int ldb,
             int M, int Kloop, int Kvalid,
             const float* __restrict__ dinv,
             float* __restrict__ Hs, int ldo)
{
    __shared__ float As[8][128];
    __shared__ float Bs[8][64];
    const int tid = threadIdx.x;
    const int m0 = blockIdx.x * 128;
    const int tx = tid & 15;
    const int ty = tid >> 4;
    const int a_mm = tid >> 1;
    const int a_kq = (tid & 1) << 2;
    const int b_kk = tid >> 5;
    const int b_nn = tid & 31;

    unsigned long long acc2[8][2];
#pragma unroll
    for (int i = 0; i < 8; i++) { acc2[i][0] = 0ull; acc2[i][1] = 0ull; }

    const int a_row = m0 + a_mm;
    const bool a_ok = a_row < M;
    const float* Aptr = A + (size_t)a_row * lda + a_kq;

    float4 av = make_float4(0.f, 0.f, 0.f, 0.f);
    float bv0 = 0.f, bv1 = 0.f;
    {
        if (a_ok) av = *(const float4*)(Aptr);
        if (b_kk < Kvalid) {
            bv0 = B[(size_t)b_kk * ldb + b_nn];
            bv1 = B[(size_t)b_kk * ldb + b_nn + 32];
        }
    }

    for (int k0 = 0; k0 < Kloop; k0 += 8) {
        As[a_kq + 0][a_mm] = av.x;
        As[a_kq + 1][a_mm] = av.y;
        As[a_kq + 2][a_mm] = av.z;
        As[a_kq + 3][a_mm] = av.w;
        Bs[b_kk][b_nn]      = bv0;
        Bs[b_kk][b_nn + 32] = bv1;
        __syncthreads();

        const int kn = k0 + 8;
        float4 av_n = make_float4(0.f, 0.f, 0.f, 0.f);
        float bv0_n = 0.f, bv1_n = 0.f;
        if (kn < Kloop) {
            if (a_ok) av_n = *(const float4*)(Aptr + kn);
            int bk = kn + b_kk;
            if (bk < Kvalid) {
                bv0_n = B[(size_t)bk * ldb + b_nn];
                bv1_n = B[(size_t)bk * ldb + b_nn + 32];
            }
        }

#pragma unroll
        for (int kk = 0; kk < 8; ++kk) {
            float4 a0 = *(const float4*)(&As[kk][ty * 8]);
            float4 a1 = *(const float4*)(&As[kk][ty * 8 + 4]);
            const unsigned long long* Bp =
                (const unsigned long long*)(&Bs[kk][tx * 4]); // 16B-aligned
            unsigned long long bp[2] = {Bp[0], Bp[1]};
            float am[8] = {a0.x, a0.y, a0.z, a0.w, a1.x, a1.y, a1.z, a1.w};
#pragma unroll
            for (int i = 0; i < 8; i++) {
                unsigned long long ad = dup_f32(am[i]);
                acc2[i][0] = fma_f32x2(ad, bp[0], acc2[i][0]);
                acc2[i][1] = fma_f32x2(ad, bp[1], acc2[i][1]);
            }
        }
        __syncthreads();
        av = av_n; bv0 = bv0_n; bv1 = bv1_n;
    }

    const int ldo4 = ldo >> 2;
#pragma unroll
    for (int i = 0; i < 8; i++) {
        int row = m0 + ty * 8 + i;
        if (row < M) {
            float di = dinv[row];
            float2 c0 = unpk_f32x2(acc2[i][0]);
            float2 c1 = unpk_f32x2(acc2[i][1]);
            size_t off = (size_t)row * ldo4 + tx;
            ((float4*)Hs)[off] = make_float4(c0.x * di, c0.y * di,
                                             c1.x * di, c1.y * di);
        }
    }
}

// ---------------- gather layer 1: Z1 = relu(dinv*(Hs[self] + sum Hs[nbr]) + b1) ----------------
__global__ __launch_bounds__(160)
void k_gather1(const float* __restrict__ Hs,
               const int* __restrict__ rowstart, const int* __restrict__ adj,
               const float* __restrict__ dinv, const float* __restrict__ bias,
               float* __restrict__ Z)
{
    const int C  = D_HP / 4;  // 160
    const int CV = D_H / 4;   // 157
    int node = blockIdx.x;
    int c = threadIdx.x;
    int rs = __ldg(&rowstart[node]);
    int re = __ldg(&rowstart[node + 1]);
    bool ok = c < CV;

    float4 acc = make_float4(0.f, 0.f, 0.f, 0.f);
    if (ok) acc = ((const float4*)Hs)[(size_t)node * C + c]; // self loop

    int j = rs;
    for (; j + 1 < re; j += 2) {
        int s0 = __ldg(&adj[j]);
        int s1 = __ldg(&adj[j + 1]);
        if (ok) {
            float4 v0 = ((const float4*)Hs)[(size_t)s0 * C + c];
            float4 v1 = ((const float4*)Hs)[(size_t)s1 * C + c];
            acc.x += v0.x + v1.x; acc.y += v0.y + v1.y;
            acc.z += v0.z + v1.z; acc.w += v0.w + v1.w;
        }
    }
    if (j < re) {
        int s0 = __ldg(&adj[j]);
        if (ok) {
            float4 v0 = ((const float4*)Hs)[(size_t)s0 * C + c];
            acc.x += v0.x; acc.y += v0.y; acc.z += v0.z; acc.w += v0.w;
        }
    }

    float4 r = make_float4(0.f, 0.f, 0.f, 0.f);
    if (ok) {
        float di = __ldg(&dinv[node]);
        float4 b = ((const float4*)bias)[c];
        r.x = fmaxf(fmaf(di, acc.x, b.x), 0.f);
        r.y = fmaxf(fmaf(di, acc.y, b.y), 0.f);
        r.z = fmaxf(fmaf(di, acc.z, b.z), 0.f);
        r.w = fmaxf(fmaf(di, acc.w, b.w), 0.f);
    }
    ((float4*)Z)[(size_t)node * C + c] = r;  // pad cols -> exact zeros
}

// ---------------- gather layer 2: Z2 = dinv*(Hs2[self] + sum Hs2[nbr]) + b2 ----------------
__global__ __launch_bounds__(256)
void k_gather2(const float* __restrict__ Hs,
               const int* __restrict__ rowstart, const int* __restrict__ adj,
               const float* __restrict__ dinv, const float* __restrict__ bias,
               float* __restrict__ Z, int n)
{
    int warp = (blockIdx.x * blockDim.x + threadIdx.x) >> 5;
    int lane = threadIdx.x & 31;
    if (warp >= n) return;
    int node = warp;
    int rs = __ldg(&rowstart[node]);
    int re = __ldg(&rowstart[node + 1]);

    float2 acc = ((const float2*)Hs)[(size_t)node * 32 + lane];

    int j = rs;
    for (; j + 1 < re; j += 2) {
        int s0 = __ldg(&adj[j]);
        int s1 = __ldg(&adj[j + 1]);
        float2 v0 = ((const float2*)Hs)[(size_t)s0 * 32 + lane];
        float2 v1 = ((const float2*)Hs)[(size_t)s1 * 32 + lane];
        acc.x += v0.x + v1.x; acc.y += v0.y + v1.y;
    }
    if (j < re) {
        int s0 = __ldg(&adj[j]);
        float2 v0 = ((const float2*)Hs)[(size_t)s0 * 32 + lane];
        acc.x += v0.x; acc.y += v0.y;
    }

    float di = __ldg(&dinv[node]);
    float2 b = ((const float2*)bias)[lane];
    float2 r = make_float2(fmaf(di, acc.x, b.x), fmaf(di, acc.y, b.y));
    ((float2*)Z)[(size_t)node * 32 + lane] = r;
}

// ---------------- decode: logits[e] = dot(Z2[src], Z2[dst]), 16 lanes/edge ----------------
__global__ void k_decode(const float* __restrict__ Z, const int* __restrict__ src,
                         const int* __restrict__ dst, float* __restrict__ out, int E)
{
    int t = blockIdx.x * blockDim.x + threadIdx.x;
    int e = t >> 4;
    int c = t & 15;
    if (e >= E) return;
    int s = src[e];
    int d = dst[e];
    float4 a = ((const float4*)Z)[(size_t)s * 16 + c];
    float4 b = ((const float4*)Z)[(size_t)d * 16 + c];
    float p = a.x * b.x + a.y * b.y + a.z * b.z + a.w * b.w;
#pragma unroll
    for (int off = 8; off >= 1; off >>= 1)
        p += __shfl_xor_sync(0xffffffffu, p, off);
    if (c == 0) out[e] = p;
}

// ---------------- launch ----------------
extern "C" void kernel_launch(void* const* d_in, const int* in_sizes, int n_in,
                              void* d_out, int out_size)
{
    const float* x  = (const float*)d_in[0];
    const int*   ei = (const int*)d_in[1];
    const float* W1 = (const float*)d_in[2];
    const float* b1 = (const float*)d_in[3];
    const float* W2 = (const float*)d_in[4];
    const float* b2 = (const float*)d_in[5];
    float* out = (float*)d_out;

    const int E = in_sizes[1] / 2;
    const int N = N_NODES;
    const int* src = ei;
    const int* dst = ei + E;

    float *buf1, *buf2, *buf3, *buf4, *dinv;
    int *deg, *rowstart, *cur, *adj;
    cudaGetSymbolAddress((void**)&buf1, g_buf1);
    cudaGetSymbolAddress((void**)&buf2, g_buf2);
    cudaGetSymbolAddress((void**)&buf3, g_buf3);
    cudaGetSymbolAddress((void**)&buf4, g_buf4);
    cudaGetSymbolAddress((void**)&dinv, g_dinv);
    cudaGetSymbolAddress((void**)&deg,  g_deg);
    cudaGetSymbolAddress((void**)&rowstart, g_rowstart);
    cudaGetSymbolAddress((void**)&cur,  g_cur);
    cudaGetSymbolAddress((void**)&adj,  g_adj);

    // CSR build (keyed by dst) + dinv
    cudaMemsetAsync(deg, 0, (size_t)N * sizeof(int), 0);
    cudaMemsetAsync(cur, 0, (size_t)N * sizeof(int), 0);
    k_count<<<(E + 255) / 256, 256>>>(dst, E, deg);
    k_dinv<<<(N + 255) / 256, 256>>>(deg, dinv, N);
    k_scan<<<1, 1024>>>(deg, rowstart, N);
    k_fill<<<(E + 255) / 256, 256>>>(src, dst, E, rowstart, cur, adj);

    // layer 1: Hs1 = dinv * (x @ W1)  [N x 640, cols >=628 exact zeros]
    {
        dim3 grid((N + 127) / 128, D_HP / 128);
        k_gemm1<<<grid, 256>>>(x, D_IN, W1, D_H, N, D_IN, D_IN, D_H,
                               dinv, buf1, D_HP);
    }
    // Z1 = relu(dinv*(self + neighbor sum) + b1)
    k_gather1<<<N, 160>>>(buf1, rowstart, adj, dinv, b1, buf2);

    // layer 2: Hs2 = dinv * (Z1 @ W2)  [N x 64]; K over padded 640 (pad = zeros)
    k_gemm2<<<(N + 127) / 128, 256>>>(buf2, D_HP, W2, D_OUT, N, D_HP, D_H,
                                      dinv, buf3, D_OUT);
    // Z2 = dinv*(self + neighbor sum) + b2
    k_gather2<<<(N * 32 + 255) / 256, 256>>>(buf3, rowstart, adj, dinv, b2, buf4, N);

    // decode
    k_decode<<<(E * 16 + 255) / 256, 256>>>(buf4, src, dst, out, E);
}